// round 12
// baseline (speedup 1.0000x reference)
#include <cuda_runtime.h>

#define NBLK 148
#define TPB  256
#define NBD  74          // blocks per direction
#define HDIM 1024
#define NJMAX 14
#define LPEP 15
#define LHLA 372
#define MLPH 4096

// ---------------- persistent scratch ----------------
__device__ float g_xg[4][LHLA][4096];   // input projections
__device__ float g_h[4][2][HDIM];       // double-buffered hidden state per chain
__device__ float g_h1[MLPH];            // MLP hidden activations
__device__ unsigned g_arrive;           // global barrier arrival counter
__device__ volatile unsigned g_gen;     // global barrier generation (monotonic)
__device__ unsigned g_flags[2][NBD];    // per-direction per-block step flags (monotonic)

__device__ __forceinline__ float sigf(float x) { return 1.0f / (1.0f + __expf(-x)); }
__device__ __forceinline__ float tanhf_fast(float x) {
    x = fminf(fmaxf(x, -15.0f), 15.0f);
    float e = __expf(2.0f * x);
    return __fdividef(e - 1.0f, e + 1.0f);
}

// Global barrier (all 148 blocks) — used only at 3 phase boundaries.
__device__ __forceinline__ void grid_barrier(unsigned &lgen) {
    __syncthreads();
    if (threadIdx.x == 0) {
        __threadfence();
        unsigned prev = atomicAdd(&g_arrive, 1u);
        unsigned target = lgen + 1u;
        if (prev == NBLK - 1u) {
            g_arrive = 0u;
            __threadfence();
            g_gen = target;
        } else {
            while ((int)(g_gen - target) < 0) { }
            __threadfence();
        }
    }
    lgen += 1u;
    __syncthreads();
}

// Per-direction barrier: release own flag, all-poll 74 flags in parallel.
__device__ __forceinline__ void dir_barrier(unsigned* flags, int lb, unsigned target, int tid) {
    __syncthreads();                               // all h stores issued (block scope)
    if (tid == 0)
        asm volatile("st.release.gpu.b32 [%0], %1;" :: "l"(flags + lb), "r"(target) : "memory");
    if (tid < NBD) {
        unsigned v;
        do {
            asm volatile("ld.acquire.gpu.b32 %0, [%1];" : "=r"(v) : "l"(flags + tid) : "memory");
        } while ((int)(v - target) < 0);
    }
    __syncthreads();
}

extern "C" __global__ void __launch_bounds__(TPB, 1)
netmhc_kernel(
    const float* __restrict__ x_pep, const float* __restrict__ x_hla,
    const float* __restrict__ p_wih_f, const float* __restrict__ p_whh_f,
    const float* __restrict__ p_bih_f, const float* __restrict__ p_bhh_f,
    const float* __restrict__ p_wih_b, const float* __restrict__ p_whh_b,
    const float* __restrict__ p_bih_b, const float* __restrict__ p_bhh_b,
    const float* __restrict__ h_wih_f, const float* __restrict__ h_whh_f,
    const float* __restrict__ h_bih_f, const float* __restrict__ h_bhh_f,
    const float* __restrict__ h_wih_b, const float* __restrict__ h_whh_b,
    const float* __restrict__ h_bih_b, const float* __restrict__ h_bhh_b,
    const float* __restrict__ w1, const float* __restrict__ b1,
    const float* __restrict__ w2, const float* __restrict__ b2,
    float* __restrict__ out)
{
    extern __shared__ float smem[];             // 229376 B: staged whh slice (fp32)
    __shared__ float s_gates[4 * NJMAX];
    __shared__ float s_c[NJMAX];
    __shared__ float s_red[TPB / 32];

    const int tid  = threadIdx.x, bid = blockIdx.x;
    const int lane = tid & 31,    warp = tid >> 5;
    unsigned lgen = g_gen;                      // global barrier epoch (monotonic)

    // ================= Phase 0: zero h0 + input projections xg =================
    const int gtid = bid * TPB + tid;
    if (gtid < 4 * 2 * HDIM) ((float*)g_h)[gtid] = 0.0f;

    {
        const float* wihs[4] = {p_wih_f, p_wih_b, h_wih_f, h_wih_b};
        const float* bihs[4] = {p_bih_f, p_bih_b, h_bih_f, h_bih_b};
        const float* bhhs[4] = {p_bhh_f, p_bhh_b, h_bhh_f, h_bhh_b};
        for (int p = gtid; p < 8192 + 24576; p += NBLK * TPB) {
            int chain, row, t0, t1;
            if (p < 8192) {
                chain = p >> 12; row = p & 4095; t0 = 0; t1 = LPEP;
            } else {
                int q = p - 8192;
                int chunk = q / 8192;
                int r2 = q - chunk * 8192;
                chain = 2 + (r2 >> 12); row = r2 & 4095;
                t0 = chunk * 124; t1 = t0 + 124;
            }
            const float* x = (chain < 2) ? x_pep : x_hla;
            const int T = (chain < 2) ? LPEP : LHLA;
            const int rev = chain & 1;
            float w[21];
            #pragma unroll
            for (int i = 0; i < 21; i++) w[i] = wihs[chain][row * 21 + i];
            const float bb = bihs[chain][row] + bhhs[chain][row];
            for (int t = t0; t < t1; t++) {
                const float* xt = x + (rev ? (T - 1 - t) : t) * 21;
                float s = bb;
                #pragma unroll
                for (int i = 0; i < 21; i++) s = fmaf(w[i], xt[i], s);
                g_xg[chain][t][row] = s;
            }
        }
    }
    grid_barrier(lgen);

    // ================= Phase 1/2: LSTM chains =================
    const int dir = bid / NBD;                     // 0 = forward, 1 = backward
    const int lb  = bid % NBD;
    const int j0  = (lb * HDIM) / NBD;
    const int j1  = ((lb + 1) * HDIM) / NBD;
    const int nj  = j1 - j0;                       // 13 or 14
    const int nrows = 4 * nj;                      // 52 or 56
    const float* whhs[4] = {p_whh_f, p_whh_b, h_whh_f, h_whh_b};

    unsigned* flags = g_flags[dir];
    unsigned bstep = flags[lb];                    // resume monotonic counter (replay-safe)

    // precompute row->xg offsets (phase-invariant)
    int rowoff[7]; bool rlive[7];
    #pragma unroll
    for (int it = 0; it < 7; it++) {
        int rl = warp + it * 8;
        rlive[it] = (rl < nrows);
        int rr = rlive[it] ? rl : 0;
        int gg = rr / nj, jj = rr - gg * nj;
        rowoff[it] = gg * HDIM + j0 + jj;
    }

    #pragma unroll 1
    for (int phase = 0; phase < 2; phase++) {
        const int chain = phase * 2 + dir;
        const int T = phase ? LHLA : LPEP;

        // stage whh rows (gate-major) into SMEM
        const float4* wsrc = (const float4*)whhs[chain];
        float4* wsm = (float4*)smem;
        for (int e = tid; e < nrows * 256; e += TPB) {
            int rl = e >> 8, off = e & 255;
            int gg = rl / nj, jj = rl - gg * nj;
            wsm[e] = wsrc[(gg * HDIM + j0 + jj) * 256 + off];
        }
        if (tid < nj) s_c[tid] = 0.0f;
        __syncthreads();

        for (int t = 0; t < T; t++) {
            const int p = t & 1;
            const float4* hsrc = (const float4*)g_h[chain][p];
            float4 hreg[8];
            #pragma unroll
            for (int i = 0; i < 8; i++) hreg[i] = __ldcg(hsrc + lane + 32 * i);

            const float* xg_t = g_xg[chain][t];
            float xgv[7];
            #pragma unroll
            for (int it = 0; it < 7; it++)         // uniform addr per warp: broadcast LDG
                xgv[it] = __ldcg(xg_t + rowoff[it]);

            #pragma unroll
            for (int it = 0; it < 7; it++) {
                const int rl = warp + it * 8;
                const float4* wrow = wsm + (rlive[it] ? rl : 0) * 256;
                float s0 = (lane == 0) ? xgv[it] : 0.0f;
                float s1 = 0.f, s2 = 0.f, s3 = 0.f;
                #pragma unroll
                for (int i = 0; i < 8; i++) {
                    float4 w4 = wrow[lane + 32 * i];   // conflict-free LDS.128
                    s0 = fmaf(w4.x, hreg[i].x, s0);
                    s1 = fmaf(w4.y, hreg[i].y, s1);
                    s2 = fmaf(w4.z, hreg[i].z, s2);
                    s3 = fmaf(w4.w, hreg[i].w, s3);
                }
                float s = (s0 + s1) + (s2 + s3);
                #pragma unroll
                for (int o = 16; o; o >>= 1) s += __shfl_xor_sync(0xffffffffu, s, o);
                if (rlive[it] && lane == 0) s_gates[rl] = s;
            }
            __syncthreads();

            if (tid < nj) {
                float iv = s_gates[tid];
                float fv = s_gates[nj + tid];
                float gv = s_gates[2 * nj + tid];
                float ov = s_gates[3 * nj + tid];
                float c = sigf(fv) * s_c[tid] + sigf(iv) * tanhf_fast(gv);
                s_c[tid] = c;
                g_h[chain][p ^ 1][j0 + tid] = sigf(ov) * tanhf_fast(c);
            }
            ++bstep;
            dir_barrier(flags, lb, bstep, tid);
        }
    }

    grid_barrier(lgen);   // join both directions before MLP

    // ================= Phase 3: MLP head =================
    {
        float* xs = smem;
        for (int k = tid; k < 4 * HDIM; k += TPB) {
            int ch = k >> 10, j = k & (HDIM - 1);
            int par = (ch < 2) ? (LPEP & 1) : (LHLA & 1);
            xs[k] = __ldcg(&g_h[ch][par][j]);
        }
        __syncthreads();

        const float4* xs4 = (const float4*)xs;
        for (int row = bid * 8 + warp; row < MLPH; row += NBLK * 8) {
            const float4* wr4 = (const float4*)(w1 + (size_t)row * 4096);
            float s = 0.0f;
            #pragma unroll 8
            for (int i = lane; i < 1024; i += 32) {
                float4 w4 = wr4[i];
                float4 x4 = xs4[i];
                s = fmaf(w4.x, x4.x, s);
                s = fmaf(w4.y, x4.y, s);
                s = fmaf(w4.z, x4.z, s);
                s = fmaf(w4.w, x4.w, s);
            }
            #pragma unroll
            for (int o = 16; o; o >>= 1) s += __shfl_xor_sync(0xffffffffu, s, o);
            if (lane == 0) g_h1[row] = fmaxf(s + b1[row], 0.0f);
        }
        grid_barrier(lgen);

        if (bid == 0) {
            const float4* h4 = (const float4*)g_h1;
            const float4* w4p = (const float4*)w2;
            float s = 0.0f;
            for (int k = tid; k < 1024; k += TPB) {
                float4 a = __ldcg(h4 + k);
                float4 b = w4p[k];
                s = fmaf(a.x, b.x, s);
                s = fmaf(a.y, b.y, s);
                s = fmaf(a.z, b.z, s);
                s = fmaf(a.w, b.w, s);
            }
            #pragma unroll
            for (int o = 16; o; o >>= 1) s += __shfl_xor_sync(0xffffffffu, s, o);
            if (lane == 0) s_red[warp] = s;
            __syncthreads();
            if (tid == 0) {
                float v = b2[0];
                #pragma unroll
                for (int wq = 0; wq < TPB / 32; wq++) v += s_red[wq];
                out[0] = v;
            }
        }
    }
}

extern "C" void kernel_launch(void* const* d_in, const int* in_sizes, int n_in,
                              void* d_out, int out_size) {
    (void)in_sizes; (void)n_in; (void)out_size;
    cudaFuncSetAttribute(netmhc_kernel,
                         cudaFuncAttributeMaxDynamicSharedMemorySize, 229376);
    netmhc_kernel<<<NBLK, TPB, 229376>>>(
        (const float*)d_in[0],  (const float*)d_in[1],
        (const float*)d_in[2],  (const float*)d_in[3],
        (const float*)d_in[4],  (const float*)d_in[5],
        (const float*)d_in[6],  (const float*)d_in[7],
        (const float*)d_in[8],  (const float*)d_in[9],
        (const float*)d_in[10], (const float*)d_in[11],
        (const float*)d_in[12], (const float*)d_in[13],
        (const float*)d_in[14], (const float*)d_in[15],
        (const float*)d_in[16], (const float*)d_in[17],
        (const float*)d_in[18], (const float*)d_in[19],
        (const float*)d_in[20], (const float*)d_in[21],
        (float*)d_out);
}

// round 16
// speedup vs baseline: 2.4939x; 2.4939x over previous
#include <cuda_runtime.h>

#define NBLK 148
#define TPB  256
#define NBD  74          // blocks per direction
#define HDIM 1024
#define NJMAX 14
#define LPEP 15
#define LHLA 372
#define MLPH 4096

// ---------------- persistent scratch ----------------
__device__ float g_xg[4][LHLA][4096];   // input projections
__device__ float g_h[4][2][HDIM];       // double-buffered hidden state per chain
__device__ float g_h1[MLPH];            // MLP hidden activations
__device__ unsigned g_arrive;           // global barrier arrival counter
__device__ volatile unsigned g_gen;     // global barrier generation (monotonic)
__device__ unsigned g_cnt[2][32];       // per-direction step arrival counter (line-padded, monotonic)

__device__ __forceinline__ float sigf(float x) { return 1.0f / (1.0f + __expf(-x)); }
__device__ __forceinline__ float tanhf_fast(float x) {
    x = fminf(fmaxf(x, -15.0f), 15.0f);
    float e = __expf(2.0f * x);
    return __fdividef(e - 1.0f, e + 1.0f);
}

// Global barrier (all 148 blocks) — only at phase boundaries.
__device__ __forceinline__ void grid_barrier(unsigned &lgen) {
    __syncthreads();
    if (threadIdx.x == 0) {
        __threadfence();
        unsigned prev = atomicAdd(&g_arrive, 1u);
        unsigned target = lgen + 1u;
        if (prev == NBLK - 1u) {
            g_arrive = 0u;
            __threadfence();
            g_gen = target;
        } else {
            while ((int)(g_gen - target) < 0) { }
            __threadfence();
        }
    }
    lgen += 1u;
    __syncthreads();
}

// Per-direction step sync: fire-and-forget aggregated arrival + single-word poll.
// Caller guarantees h-slice stores precede via the leading __syncthreads.
__device__ __forceinline__ void dir_sync(unsigned* cnt, unsigned target) {
    __syncthreads();                    // all h stores of this block ordered before release
    if (threadIdx.x == 0) {
        asm volatile("red.release.gpu.global.add.u32 [%0], %1;" :: "l"(cnt), "r"(1u) : "memory");
        unsigned v;
        do {
            asm volatile("ld.acquire.gpu.global.u32 %0, [%1];" : "=r"(v) : "l"(cnt) : "memory");
        } while ((int)(v - target) < 0);
    }
    __syncthreads();                    // propagate acquire to all warps
}

extern "C" __global__ void __launch_bounds__(TPB, 1)
netmhc_kernel(
    const float* __restrict__ x_pep, const float* __restrict__ x_hla,
    const float* __restrict__ p_wih_f, const float* __restrict__ p_whh_f,
    const float* __restrict__ p_bih_f, const float* __restrict__ p_bhh_f,
    const float* __restrict__ p_wih_b, const float* __restrict__ p_whh_b,
    const float* __restrict__ p_bih_b, const float* __restrict__ p_bhh_b,
    const float* __restrict__ h_wih_f, const float* __restrict__ h_whh_f,
    const float* __restrict__ h_bih_f, const float* __restrict__ h_bhh_f,
    const float* __restrict__ h_wih_b, const float* __restrict__ h_whh_b,
    const float* __restrict__ h_bih_b, const float* __restrict__ h_bhh_b,
    const float* __restrict__ w1, const float* __restrict__ b1,
    const float* __restrict__ w2, const float* __restrict__ b2,
    float* __restrict__ out)
{
    extern __shared__ float smem[];             // 229376 B: staged whh slice (fp32)
    __shared__ float s_gates[4 * NJMAX];
    __shared__ float s_c[NJMAX];
    __shared__ float s_red[TPB / 32];

    const int tid  = threadIdx.x, bid = blockIdx.x;
    const int lane = tid & 31,    warp = tid >> 5;
    const int dir = bid / NBD;                  // 0 = forward, 1 = backward
    const int lb  = bid % NBD;
    unsigned lgen = g_gen;                      // global barrier epoch (monotonic)

    // Counter base for this replay: read BEFORE the first grid_barrier (no
    // increments can be in flight; grid_barrier orders read < all arrivals).
    unsigned* cw = &g_cnt[dir][0];
    unsigned cnt_base;
    asm volatile("ld.global.u32 %0, [%1];" : "=r"(cnt_base) : "l"(cw) : "memory");

    // ================= Phase 0: zero h0 + input projections xg =================
    const int gtid = bid * TPB + tid;
    if (gtid < 4 * 2 * HDIM) ((float*)g_h)[gtid] = 0.0f;

    {
        const float* wihs[4] = {p_wih_f, p_wih_b, h_wih_f, h_wih_b};
        const float* bihs[4] = {p_bih_f, p_bih_b, h_bih_f, h_bih_b};
        const float* bhhs[4] = {p_bhh_f, p_bhh_b, h_bhh_f, h_bhh_b};
        for (int p = gtid; p < 8192 + 24576; p += NBLK * TPB) {
            int chain, row, t0, t1;
            if (p < 8192) {
                chain = p >> 12; row = p & 4095; t0 = 0; t1 = LPEP;
            } else {
                int q = p - 8192;
                int chunk = q / 8192;
                int r2 = q - chunk * 8192;
                chain = 2 + (r2 >> 12); row = r2 & 4095;
                t0 = chunk * 124; t1 = t0 + 124;
            }
            const float* x = (chain < 2) ? x_pep : x_hla;
            const int T = (chain < 2) ? LPEP : LHLA;
            const int rev = chain & 1;
            float w[21];
            #pragma unroll
            for (int i = 0; i < 21; i++) w[i] = wihs[chain][row * 21 + i];
            const float bb = bihs[chain][row] + bhhs[chain][row];
            for (int t = t0; t < t1; t++) {
                const float* xt = x + (rev ? (T - 1 - t) : t) * 21;
                float s = bb;
                #pragma unroll
                for (int i = 0; i < 21; i++) s = fmaf(w[i], xt[i], s);
                g_xg[chain][t][row] = s;
            }
        }
    }
    grid_barrier(lgen);

    // ================= Phase 1/2: LSTM chains =================
    const int j0  = (lb * HDIM) / NBD;
    const int j1  = ((lb + 1) * HDIM) / NBD;
    const int nj  = j1 - j0;                       // 13 or 14
    const int nrows = 4 * nj;                      // 52 or 56
    const float* whhs[4] = {p_whh_f, p_whh_b, h_whh_f, h_whh_b};

    unsigned tgt = cnt_base;                       // arrival target (monotonic, replay-safe)

    // precompute row->xg offsets (phase-invariant)
    int rowoff[7]; bool rlive[7];
    #pragma unroll
    for (int it = 0; it < 7; it++) {
        int rl = warp + it * 8;
        rlive[it] = (rl < nrows);
        int rr = rlive[it] ? rl : 0;
        int gg = rr / nj, jj = rr - gg * nj;
        rowoff[it] = gg * HDIM + j0 + jj;
    }

    #pragma unroll 1
    for (int phase = 0; phase < 2; phase++) {
        const int chain = phase * 2 + dir;
        const int T = phase ? LHLA : LPEP;

        // stage whh rows (gate-major) into SMEM
        const float4* wsrc = (const float4*)whhs[chain];
        float4* wsm = (float4*)smem;
        for (int e = tid; e < nrows * 256; e += TPB) {
            int rl = e >> 8, off = e & 255;
            int gg = rl / nj, jj = rl - gg * nj;
            wsm[e] = wsrc[(gg * HDIM + j0 + jj) * 256 + off];
        }
        if (tid < nj) s_c[tid] = 0.0f;
        __syncthreads();

        // software-pipelined xg preload for t=0
        float xgv[7];
        #pragma unroll
        for (int it = 0; it < 7; it++)
            xgv[it] = __ldcg(g_xg[chain][0] + rowoff[it]);

        for (int t = 0; t < T; t++) {
            const int p = t & 1;
            const float4* hsrc = (const float4*)g_h[chain][p];
            float4 hreg[8];
            #pragma unroll
            for (int i = 0; i < 8; i++) hreg[i] = __ldcg(hsrc + lane + 32 * i);

            #pragma unroll
            for (int it = 0; it < 7; it++) {
                const int rl = warp + it * 8;
                const float4* wrow = wsm + (rlive[it] ? rl : 0) * 256;
                float s0 = (lane == 0) ? xgv[it] : 0.0f;
                float s1 = 0.f, s2 = 0.f, s3 = 0.f;
                #pragma unroll
                for (int i = 0; i < 8; i++) {
                    float4 w4 = wrow[lane + 32 * i];   // conflict-free LDS.128
                    s0 = fmaf(w4.x, hreg[i].x, s0);
                    s1 = fmaf(w4.y, hreg[i].y, s1);
                    s2 = fmaf(w4.z, hreg[i].z, s2);
                    s3 = fmaf(w4.w, hreg[i].w, s3);
                }
                float s = (s0 + s1) + (s2 + s3);
                #pragma unroll
                for (int o = 16; o; o >>= 1) s += __shfl_xor_sync(0xffffffffu, s, o);
                if (rlive[it] && lane == 0) s_gates[rl] = s;
            }
            __syncthreads();

            if (tid < nj) {
                float iv = s_gates[tid];
                float fv = s_gates[nj + tid];
                float gv = s_gates[2 * nj + tid];
                float ov = s_gates[3 * nj + tid];
                float c = sigf(fv) * s_c[tid] + sigf(iv) * tanhf_fast(gv);
                s_c[tid] = c;
                g_h[chain][p ^ 1][j0 + tid] = sigf(ov) * tanhf_fast(c);
            }

            // prefetch next step's xg (overlaps the sync wait below)
            const int tn = (t + 1 < T) ? t + 1 : t;
            #pragma unroll
            for (int it = 0; it < 7; it++)
                xgv[it] = __ldcg(g_xg[chain][tn] + rowoff[it]);

            tgt += NBD;
            dir_sync(cw, tgt);
        }
    }

    grid_barrier(lgen);   // join both directions before MLP

    // ================= Phase 3: MLP head =================
    {
        float* xs = smem;
        for (int k = tid; k < 4 * HDIM; k += TPB) {
            int ch = k >> 10, j = k & (HDIM - 1);
            int par = (ch < 2) ? (LPEP & 1) : (LHLA & 1);
            xs[k] = __ldcg(&g_h[ch][par][j]);
        }
        __syncthreads();

        const float4* xs4 = (const float4*)xs;
        for (int row = bid * 8 + warp; row < MLPH; row += NBLK * 8) {
            const float4* wr4 = (const float4*)(w1 + (size_t)row * 4096);
            float s = 0.0f;
            #pragma unroll 8
            for (int i = lane; i < 1024; i += 32) {
                float4 w4 = wr4[i];
                float4 x4 = xs4[i];
                s = fmaf(w4.x, x4.x, s);
                s = fmaf(w4.y, x4.y, s);
                s = fmaf(w4.z, x4.z, s);
                s = fmaf(w4.w, x4.w, s);
            }
            #pragma unroll
            for (int o = 16; o; o >>= 1) s += __shfl_xor_sync(0xffffffffu, s, o);
            if (lane == 0) g_h1[row] = fmaxf(s + b1[row], 0.0f);
        }
        grid_barrier(lgen);

        if (bid == 0) {
            const float4* h4 = (const float4*)g_h1;
            const float4* w4p = (const float4*)w2;
            float s = 0.0f;
            for (int k = tid; k < 1024; k += TPB) {
                float4 a = __ldcg(h4 + k);
                float4 b = w4p[k];
                s = fmaf(a.x, b.x, s);
                s = fmaf(a.y, b.y, s);
                s = fmaf(a.z, b.z, s);
                s = fmaf(a.w, b.w, s);
            }
            #pragma unroll
            for (int o = 16; o; o >>= 1) s += __shfl_xor_sync(0xffffffffu, s, o);
            if (lane == 0) s_red[warp] = s;
            __syncthreads();
            if (tid == 0) {
                float v = b2[0];
                #pragma unroll
                for (int wq = 0; wq < TPB / 32; wq++) v += s_red[wq];
                out[0] = v;
            }
        }
    }
}

extern "C" void kernel_launch(void* const* d_in, const int* in_sizes, int n_in,
                              void* d_out, int out_size) {
    (void)in_sizes; (void)n_in; (void)out_size;
    cudaFuncSetAttribute(netmhc_kernel,
                         cudaFuncAttributeMaxDynamicSharedMemorySize, 229376);
    netmhc_kernel<<<NBLK, TPB, 229376>>>(
        (const float*)d_in[0],  (const float*)d_in[1],
        (const float*)d_in[2],  (const float*)d_in[3],
        (const float*)d_in[4],  (const float*)d_in[5],
        (const float*)d_in[6],  (const float*)d_in[7],
        (const float*)d_in[8],  (const float*)d_in[9],
        (const float*)d_in[10], (const float*)d_in[11],
        (const float*)d_in[12], (const float*)d_in[13],
        (const float*)d_in[14], (const float*)d_in[15],
        (const float*)d_in[16], (const float*)d_in[17],
        (const float*)d_in[18], (const float*)d_in[19],
        (const float*)d_in[20], (const float*)d_in[21],
        (float*)d_out);
}